// round 10
// baseline (speedup 1.0000x reference)
#include <cuda_runtime.h>
#include <cuda_fp16.h>

#define NN   100000
#define INF  128
#define OUTF 64
#define NE_MAX 3200000
#define SCAN_B 1024
#define NBLK  ((NN + SCAN_B - 1) / SCAN_B)   // 98
#define WPAD  72
#define APITCH 132                            // A-tile smem pitch (uints)
#define GEMM_SMEM ((INF * WPAD + 128 * APITCH) * 4)   // 104,448 B

// Scratch (allocation-free rule: __device__ globals)
__device__ __half g_xws_h[(size_t)NN * OUTF]; // fp16 (X@W)*rsqrt(deg_out)
__device__ int    g_deg_out[NN];
__device__ int    g_deg_in[NN];
__device__ int    g_row_off[NN];
__device__ int    g_cursor[NN];
__device__ int    g_csr_src[NE_MAX];
__device__ int    g_blocksum[NBLK];
__device__ int    g_blockoff[NBLK];

// ---------------------------------------------------------------------------
__global__ void zero_kernel() {
    int t = blockIdx.x * blockDim.x + threadIdx.x;
    int stride = gridDim.x * blockDim.x;
    for (int j = t; j < NN; j += stride) {
        g_deg_out[j] = 0;
        g_deg_in[j]  = 0;
    }
}

// ---------------------------------------------------------------------------
// Degree histogram, int4-vectorized: 4 edges per thread iteration.
// ---------------------------------------------------------------------------
__global__ void degree_kernel(const int* __restrict__ src,
                              const int* __restrict__ dst, int E) {
    int stride = gridDim.x * blockDim.x;
    int t = blockIdx.x * blockDim.x + threadIdx.x;
    int E4 = E >> 2;
    const int4* s4 = (const int4*)src;
    const int4* d4 = (const int4*)dst;
    for (int i = t; i < E4; i += stride) {
        int4 s = __ldg(&s4[i]);
        int4 d = __ldg(&d4[i]);
        if ((unsigned)s.x < NN) atomicAdd(&g_deg_out[s.x], 1);
        if ((unsigned)s.y < NN) atomicAdd(&g_deg_out[s.y], 1);
        if ((unsigned)s.z < NN) atomicAdd(&g_deg_out[s.z], 1);
        if ((unsigned)s.w < NN) atomicAdd(&g_deg_out[s.w], 1);
        if ((unsigned)d.x < NN) atomicAdd(&g_deg_in[d.x], 1);
        if ((unsigned)d.y < NN) atomicAdd(&g_deg_in[d.y], 1);
        if ((unsigned)d.z < NN) atomicAdd(&g_deg_in[d.z], 1);
        if ((unsigned)d.w < NN) atomicAdd(&g_deg_in[d.w], 1);
    }
    for (int e = E4 * 4 + t; e < E; e += stride) {   // tail
        int s = src[e], d = dst[e];
        if ((unsigned)s < NN) atomicAdd(&g_deg_out[s], 1);
        if ((unsigned)d < NN) atomicAdd(&g_deg_in[d],  1);
    }
}

// ---------------------------------------------------------------------------
// Exclusive scan of g_deg_in -> g_row_off  (3 passes)
// ---------------------------------------------------------------------------
__global__ __launch_bounds__(SCAN_B) void scan_local_kernel() {
    __shared__ int sm[SCAN_B];
    int tid = threadIdx.x;
    int gid = blockIdx.x * SCAN_B + tid;
    int val = (gid < NN) ? g_deg_in[gid] : 0;
    sm[tid] = val;
    __syncthreads();
    #pragma unroll
    for (int off = 1; off < SCAN_B; off <<= 1) {
        int t = (tid >= off) ? sm[tid - off] : 0;
        __syncthreads();
        sm[tid] += t;
        __syncthreads();
    }
    if (gid < NN) g_row_off[gid] = sm[tid] - val;
    if (tid == SCAN_B - 1) g_blocksum[blockIdx.x] = sm[tid];
}

__global__ __launch_bounds__(128) void scan_blocks_kernel() {
    __shared__ int sm[128];
    int t = threadIdx.x;
    int val = (t < NBLK) ? g_blocksum[t] : 0;
    sm[t] = val;
    __syncthreads();
    #pragma unroll
    for (int off = 1; off < 128; off <<= 1) {
        int u = (t >= off) ? sm[t - off] : 0;
        __syncthreads();
        sm[t] += u;
        __syncthreads();
    }
    if (t < NBLK) g_blockoff[t] = sm[t] - val;
}

__global__ __launch_bounds__(SCAN_B) void scan_add_kernel() {
    int gid = blockIdx.x * SCAN_B + threadIdx.x;
    if (gid < NN) {
        int v = g_row_off[gid] + g_blockoff[blockIdx.x];
        g_row_off[gid] = v;
        g_cursor[gid]  = v;
    }
}

// ---------------------------------------------------------------------------
// CSR fill, int4-vectorized: 4 edges per thread iteration.
// ---------------------------------------------------------------------------
__global__ void csr_fill_kernel(const int* __restrict__ src,
                                const int* __restrict__ dst, int E) {
    int stride = gridDim.x * blockDim.x;
    int t = blockIdx.x * blockDim.x + threadIdx.x;
    int E4 = E >> 2;
    const int4* s4 = (const int4*)src;
    const int4* d4 = (const int4*)dst;
    for (int i = t; i < E4; i += stride) {
        int4 s = __ldg(&s4[i]);
        int4 d = __ldg(&d4[i]);
        if ((unsigned)s.x < NN && (unsigned)d.x < NN)
            g_csr_src[atomicAdd(&g_cursor[d.x], 1)] = s.x;
        if ((unsigned)s.y < NN && (unsigned)d.y < NN)
            g_csr_src[atomicAdd(&g_cursor[d.y], 1)] = s.y;
        if ((unsigned)s.z < NN && (unsigned)d.z < NN)
            g_csr_src[atomicAdd(&g_cursor[d.z], 1)] = s.z;
        if ((unsigned)s.w < NN && (unsigned)d.w < NN)
            g_csr_src[atomicAdd(&g_cursor[d.w], 1)] = s.w;
    }
    for (int e = E4 * 4 + t; e < E; e += stride) {   // tail
        int s = src[e], d = dst[e];
        if ((unsigned)s < NN && (unsigned)d < NN)
            g_csr_src[atomicAdd(&g_cursor[d], 1)] = s;
    }
}

// ---------------------------------------------------------------------------
// Tensor-core GEMM: xws = fp16( (A @ W) * rsqrt(max(deg_out,1)) )
// A tile (128 rows) staged in smem via coalesced LDG.128 + tf32 convert;
// fragment loads via conflict-free LDS.32 (pitch 132: bank = 4g+tg, distinct).
// ---------------------------------------------------------------------------
__global__ __launch_bounds__(256) void gemm_mma_kernel(
    const float* __restrict__ A, const float* __restrict__ W, int n) {
    extern __shared__ unsigned sh[];
    unsigned* Ws = sh;                 // [128][WPAD]
    unsigned* As = sh + INF * WPAD;    // [128][APITCH]
    int tid = threadIdx.x;

    for (int i = tid; i < INF * OUTF; i += 256) {
        int k = i >> 6, c = i & 63;
        unsigned t;
        asm("cvt.rna.tf32.f32 %0, %1;" : "=r"(t) : "f"(W[i]));
        Ws[k * WPAD + c] = t;
    }

    int rowbase = blockIdx.x * 128;
    for (int i = tid; i < 128 * 32; i += 256) {     // 4096 float4 loads
        int r  = i >> 5;
        int c4 = i & 31;
        int gr = rowbase + r; if (gr >= n) gr = n - 1;
        float4 v = __ldg((const float4*)(A + (size_t)gr * INF) + c4);
        uint4 tv;
        asm("cvt.rna.tf32.f32 %0, %1;" : "=r"(tv.x) : "f"(v.x));
        asm("cvt.rna.tf32.f32 %0, %1;" : "=r"(tv.y) : "f"(v.y));
        asm("cvt.rna.tf32.f32 %0, %1;" : "=r"(tv.z) : "f"(v.z));
        asm("cvt.rna.tf32.f32 %0, %1;" : "=r"(tv.w) : "f"(v.w));
        *(uint4*)(As + r * APITCH + c4 * 4) = tv;   // 16B-aligned (132*4=528)
    }
    __syncthreads();

    int warp = tid >> 5;
    int lane = tid & 31;
    int g  = lane >> 2;
    int tg = lane & 3;

    int rl_loc = warp * 16 + g;        // local row (lo)
    const unsigned* Alo = As + rl_loc * APITCH;
    const unsigned* Ahi = Alo + 8 * APITCH;

    int r_lo = rowbase + rl_loc;
    int r_hi = r_lo + 8;

    float acc[8][4];
    #pragma unroll
    for (int nt = 0; nt < 8; nt++)
        #pragma unroll
        for (int c = 0; c < 4; c++) acc[nt][c] = 0.f;

    #pragma unroll
    for (int kk = 0; kk < 16; kk++) {
        int k0 = kk * 8;
        unsigned a0 = Alo[k0 + tg];
        unsigned a1 = Ahi[k0 + tg];
        unsigned a2 = Alo[k0 + tg + 4];
        unsigned a3 = Ahi[k0 + tg + 4];
        #pragma unroll
        for (int nt = 0; nt < 8; nt++) {
            unsigned b0 = Ws[(k0 + tg) * WPAD + nt * 8 + g];
            unsigned b1 = Ws[(k0 + tg + 4) * WPAD + nt * 8 + g];
            asm("mma.sync.aligned.m16n8k8.row.col.f32.tf32.tf32.f32 "
                "{%0,%1,%2,%3}, {%4,%5,%6,%7}, {%8,%9}, {%0,%1,%2,%3};"
                : "+f"(acc[nt][0]), "+f"(acc[nt][1]),
                  "+f"(acc[nt][2]), "+f"(acc[nt][3])
                : "r"(a0), "r"(a1), "r"(a2), "r"(a3), "r"(b0), "r"(b1));
        }
    }

    float s_lo = 1.f, s_hi = 1.f;
    if (r_lo < n) {
        int dg = g_deg_out[r_lo];
        s_lo = rsqrtf((float)(dg > 0 ? dg : 1));
    }
    if (r_hi < n) {
        int dg = g_deg_out[r_hi];
        s_hi = rsqrtf((float)(dg > 0 ? dg : 1));
    }
    #pragma unroll
    for (int nt = 0; nt < 8; nt++) {
        int col = nt * 8 + 2 * tg;
        if (r_lo < n) {
            __half2 h = __floats2half2_rn(acc[nt][0] * s_lo, acc[nt][1] * s_lo);
            *(__half2*)&g_xws_h[(size_t)r_lo * OUTF + col] = h;
        }
        if (r_hi < n) {
            __half2 h = __floats2half2_rn(acc[nt][2] * s_hi, acc[nt][3] * s_hi);
            *(__half2*)&g_xws_h[(size_t)r_hi * OUTF + col] = h;
        }
    }
}

// ---------------------------------------------------------------------------
// Aggregate: one warp per dst node, MLP=8 (R9 scheme, measured best).
// ---------------------------------------------------------------------------
__global__ __launch_bounds__(256) void aggregate_kernel(
    float* __restrict__ out, const float* __restrict__ b, int n) {
    int warp = (blockIdx.x * blockDim.x + threadIdx.x) >> 5;
    if (warp >= n) return;
    int lane = threadIdx.x & 31;

    int start = g_row_off[warp];
    int deg   = g_deg_in[warp];

    float accx = 0.f, accy = 0.f;
    const __half2* base = (const __half2*)g_xws_h;

    for (int e0 = 0; e0 < deg; e0 += 32) {
        int me  = e0 + lane;
        int s   = (me < deg) ? __ldg(&g_csr_src[start + me]) : 0;
        int cnt = deg - e0; if (cnt > 32) cnt = 32;
        int j = 0;
        #pragma unroll 1
        for (; j + 8 <= cnt; j += 8) {
            int si[8];
            #pragma unroll
            for (int q = 0; q < 8; q++)
                si[q] = __shfl_sync(0xffffffffu, s, j + q);
            __half2 v[8];
            #pragma unroll
            for (int q = 0; q < 8; q++)
                v[q] = __ldg(base + (size_t)si[q] * 32 + lane);
            #pragma unroll
            for (int q = 0; q < 8; q++) {
                float2 f = __half22float2(v[q]);
                accx += f.x;
                accy += f.y;
            }
        }
        for (; j < cnt; j++) {
            int sj = __shfl_sync(0xffffffffu, s, j);
            float2 f = __half22float2(__ldg(base + (size_t)sj * 32 + lane));
            accx += f.x;
            accy += f.y;
        }
    }

    float sc = rsqrtf((float)(deg > 0 ? deg : 1));
    float2 bb = __ldg((const float2*)b + lane);
    float2 r;
    r.x = fmaxf(fmaf(accx, sc, bb.x), 0.f);
    r.y = fmaxf(fmaf(accy, sc, bb.y), 0.f);
    ((float2*)out)[(size_t)warp * 32 + lane] = r;
}

// ---------------------------------------------------------------------------
extern "C" void kernel_launch(void* const* d_in, const int* in_sizes, int n_in,
                              void* d_out, int out_size) {
    const float* in_feat = (const float*)d_in[0];
    const int*   src     = (const int*)d_in[1];
    const int*   dst     = (const int*)d_in[2];
    const float* W       = (const float*)d_in[3];
    const float* b       = (const float*)d_in[4];
    float*       out     = (float*)d_out;

    int n = in_sizes[0] / INF;
    int E = in_sizes[1];

    static bool attr_done = false;
    if (!attr_done) {
        cudaFuncSetAttribute(gemm_mma_kernel,
                             cudaFuncAttributeMaxDynamicSharedMemorySize,
                             GEMM_SMEM);
        attr_done = true;
    }

    zero_kernel<<<512, 256>>>();
    degree_kernel<<<2048, 256>>>(src, dst, E);
    scan_local_kernel<<<NBLK, SCAN_B>>>();
    scan_blocks_kernel<<<1, 128>>>();
    scan_add_kernel<<<NBLK, SCAN_B>>>();
    csr_fill_kernel<<<2048, 256>>>(src, dst, E);
    gemm_mma_kernel<<<(n + 127) / 128, 256, GEMM_SMEM>>>(in_feat, W, n);
    aggregate_kernel<<<(n * 32 + 255) / 256, 256>>>(out, b, n);
}

// round 11
// speedup vs baseline: 1.0477x; 1.0477x over previous
#include <cuda_runtime.h>
#include <cuda_fp16.h>

#define NN   100000
#define INF  128
#define OUTF 64
#define NE_MAX 4000000            // 3.2M edges + worst-case pad (7/node)
#define SCAN_B 1024
#define NBLK  ((NN + SCAN_B - 1) / SCAN_B)   // 98
#define WPAD  72

// Scratch (allocation-free rule: __device__ globals)
// Row NN of g_xws_h is a dedicated all-zero row used for CSR padding.
__device__ __half g_xws_h[(size_t)(NN + 1) * OUTF];
__device__ int    g_deg_out[NN];
__device__ int    g_deg_in[NN];
__device__ int    g_row_off[NN];   // padded CSR row start (by dst)
__device__ int    g_cursor[NN];
__device__ int    g_csr_src[NE_MAX];
__device__ int    g_blocksum[NBLK];
__device__ int    g_blockoff[NBLK];

// ---------------------------------------------------------------------------
__global__ void zero_kernel() {
    int t = blockIdx.x * blockDim.x + threadIdx.x;
    int stride = gridDim.x * blockDim.x;
    for (int j = t; j < NN; j += stride) {
        g_deg_out[j] = 0;
        g_deg_in[j]  = 0;
    }
    if (blockIdx.x == 0 && t < OUTF)          // keep the pad row zero
        g_xws_h[(size_t)NN * OUTF + t] = __float2half(0.f);
}

// ---------------------------------------------------------------------------
__global__ void degree_kernel(const int* __restrict__ src,
                              const int* __restrict__ dst, int E) {
    int stride = gridDim.x * blockDim.x;
    for (int e = blockIdx.x * blockDim.x + threadIdx.x; e < E; e += stride) {
        int s = src[e], d = dst[e];
        if ((unsigned)s < NN) atomicAdd(&g_deg_out[s], 1);
        if ((unsigned)d < NN) atomicAdd(&g_deg_in[d],  1);
    }
}

// ---------------------------------------------------------------------------
// Exclusive scan of PADDED degrees ((deg+7)&~7) -> g_row_off  (3 passes)
// ---------------------------------------------------------------------------
__global__ __launch_bounds__(SCAN_B) void scan_local_kernel() {
    __shared__ int sm[SCAN_B];
    int tid = threadIdx.x;
    int gid = blockIdx.x * SCAN_B + tid;
    int val = 0;
    if (gid < NN) val = (g_deg_in[gid] + 7) & ~7;
    sm[tid] = val;
    __syncthreads();
    #pragma unroll
    for (int off = 1; off < SCAN_B; off <<= 1) {
        int t = (tid >= off) ? sm[tid - off] : 0;
        __syncthreads();
        sm[tid] += t;
        __syncthreads();
    }
    if (gid < NN) g_row_off[gid] = sm[tid] - val;
    if (tid == SCAN_B - 1) g_blocksum[blockIdx.x] = sm[tid];
}

__global__ __launch_bounds__(128) void scan_blocks_kernel() {
    __shared__ int sm[128];
    int t = threadIdx.x;
    int val = (t < NBLK) ? g_blocksum[t] : 0;
    sm[t] = val;
    __syncthreads();
    #pragma unroll
    for (int off = 1; off < 128; off <<= 1) {
        int u = (t >= off) ? sm[t - off] : 0;
        __syncthreads();
        sm[t] += u;
        __syncthreads();
    }
    if (t < NBLK) g_blockoff[t] = sm[t] - val;
}

__global__ __launch_bounds__(SCAN_B) void scan_add_kernel() {
    int gid = blockIdx.x * SCAN_B + threadIdx.x;
    if (gid < NN) {
        int v = g_row_off[gid] + g_blockoff[blockIdx.x];
        g_row_off[gid] = v;
        g_cursor[gid]  = v;
    }
}

// ---------------------------------------------------------------------------
__global__ void csr_fill_kernel(const int* __restrict__ src,
                                const int* __restrict__ dst, int E) {
    int stride = gridDim.x * blockDim.x;
    for (int e = blockIdx.x * blockDim.x + threadIdx.x; e < E; e += stride) {
        int s = src[e], d = dst[e];
        if ((unsigned)s >= NN || (unsigned)d >= NN) continue;
        int pos = atomicAdd(&g_cursor[d], 1);
        g_csr_src[pos] = s;
    }
}

// Fill pad slots [row_off+deg, row_off+pdeg) with the zero-row index NN.
__global__ void csr_pad_kernel() {
    int t = blockIdx.x * blockDim.x + threadIdx.x;
    int stride = gridDim.x * blockDim.x;
    for (int d = t; d < NN; d += stride) {
        int deg  = g_deg_in[d];
        int pdeg = (deg + 7) & ~7;
        int base = g_row_off[d];
        for (int p = deg; p < pdeg; p++)
            g_csr_src[base + p] = NN;
    }
}

// ---------------------------------------------------------------------------
// Tensor-core GEMM: xws = fp16( (A @ W) * rsqrt(max(deg_out,1)) )
// mma.sync.m16n8k8 tf32. One warp = 16 rows x 64 cols. (R9 version, trusted.)
// ---------------------------------------------------------------------------
__global__ __launch_bounds__(256) void gemm_mma_kernel(
    const float* __restrict__ A, const float* __restrict__ W, int n) {
    __shared__ unsigned Ws[INF][WPAD];
    int tid = threadIdx.x;
    for (int i = tid; i < INF * OUTF; i += 256) {
        int k = i >> 6, c = i & 63;
        unsigned t;
        asm("cvt.rna.tf32.f32 %0, %1;" : "=r"(t) : "f"(W[i]));
        Ws[k][c] = t;
    }
    __syncthreads();

    int warp = tid >> 5;
    int lane = tid & 31;
    int g  = lane >> 2;
    int tg = lane & 3;
    int row0 = (blockIdx.x * 8 + warp) * 16;

    int r_lo = row0 + g;
    int r_hi = row0 + g + 8;
    int r_lo_c = r_lo < n ? r_lo : n - 1;
    int r_hi_c = r_hi < n ? r_hi : n - 1;
    const float* Alo = A + (size_t)r_lo_c * INF;
    const float* Ahi = A + (size_t)r_hi_c * INF;

    float acc[8][4];
    #pragma unroll
    for (int nt = 0; nt < 8; nt++)
        #pragma unroll
        for (int c = 0; c < 4; c++) acc[nt][c] = 0.f;

    #pragma unroll
    for (int kk = 0; kk < 16; kk++) {
        int k0 = kk * 8;
        float a0f = __ldg(&Alo[k0 + tg]);
        float a1f = __ldg(&Ahi[k0 + tg]);
        float a2f = __ldg(&Alo[k0 + tg + 4]);
        float a3f = __ldg(&Ahi[k0 + tg + 4]);
        unsigned a0, a1, a2, a3;
        asm("cvt.rna.tf32.f32 %0, %1;" : "=r"(a0) : "f"(a0f));
        asm("cvt.rna.tf32.f32 %0, %1;" : "=r"(a1) : "f"(a1f));
        asm("cvt.rna.tf32.f32 %0, %1;" : "=r"(a2) : "f"(a2f));
        asm("cvt.rna.tf32.f32 %0, %1;" : "=r"(a3) : "f"(a3f));
        #pragma unroll
        for (int nt = 0; nt < 8; nt++) {
            unsigned b0 = Ws[k0 + tg][nt * 8 + g];
            unsigned b1 = Ws[k0 + tg + 4][nt * 8 + g];
            asm("mma.sync.aligned.m16n8k8.row.col.f32.tf32.tf32.f32 "
                "{%0,%1,%2,%3}, {%4,%5,%6,%7}, {%8,%9}, {%0,%1,%2,%3};"
                : "+f"(acc[nt][0]), "+f"(acc[nt][1]),
                  "+f"(acc[nt][2]), "+f"(acc[nt][3])
                : "r"(a0), "r"(a1), "r"(a2), "r"(a3), "r"(b0), "r"(b1));
        }
    }

    float s_lo = 1.f, s_hi = 1.f;
    if (r_lo < n) {
        int dg = g_deg_out[r_lo];
        s_lo = rsqrtf((float)(dg > 0 ? dg : 1));
    }
    if (r_hi < n) {
        int dg = g_deg_out[r_hi];
        s_hi = rsqrtf((float)(dg > 0 ? dg : 1));
    }
    #pragma unroll
    for (int nt = 0; nt < 8; nt++) {
        int col = nt * 8 + 2 * tg;
        if (r_lo < n) {
            __half2 h = __floats2half2_rn(acc[nt][0] * s_lo, acc[nt][1] * s_lo);
            *(__half2*)&g_xws_h[(size_t)r_lo * OUTF + col] = h;
        }
        if (r_hi < n) {
            __half2 h = __floats2half2_rn(acc[nt][2] * s_hi, acc[nt][3] * s_hi);
            *(__half2*)&g_xws_h[(size_t)r_hi * OUTF + col] = h;
        }
    }
}

// ---------------------------------------------------------------------------
// Aggregate: one warp per dst node, MLP=8. Rows padded to multiples of 8 with
// the zero row -> inner loop is pure unrolled-8 batches, no scalar tail.
// ---------------------------------------------------------------------------
__global__ __launch_bounds__(256) void aggregate_kernel(
    float* __restrict__ out, const float* __restrict__ b, int n) {
    int warp = (blockIdx.x * blockDim.x + threadIdx.x) >> 5;
    if (warp >= n) return;
    int lane = threadIdx.x & 31;

    int start = g_row_off[warp];
    int deg   = g_deg_in[warp];
    int pdeg  = (deg + 7) & ~7;

    float accx = 0.f, accy = 0.f;
    const __half2* base = (const __half2*)g_xws_h;

    for (int e0 = 0; e0 < pdeg; e0 += 32) {
        int me  = e0 + lane;
        int s   = (me < pdeg) ? __ldg(&g_csr_src[start + me]) : NN;
        int cnt = pdeg - e0; if (cnt > 32) cnt = 32;   // multiple of 8
        #pragma unroll 1
        for (int j = 0; j < cnt; j += 8) {
            int si[8];
            #pragma unroll
            for (int q = 0; q < 8; q++)
                si[q] = __shfl_sync(0xffffffffu, s, j + q);
            __half2 v[8];
            #pragma unroll
            for (int q = 0; q < 8; q++)
                v[q] = __ldg(base + (size_t)si[q] * 32 + lane);
            #pragma unroll
            for (int q = 0; q < 8; q++) {
                float2 f = __half22float2(v[q]);
                accx += f.x;
                accy += f.y;
            }
        }
    }

    float sc = rsqrtf((float)(deg > 0 ? deg : 1));
    float2 bb = __ldg((const float2*)b + lane);
    float2 r;
    r.x = fmaxf(fmaf(accx, sc, bb.x), 0.f);
    r.y = fmaxf(fmaf(accy, sc, bb.y), 0.f);
    ((float2*)out)[(size_t)warp * 32 + lane] = r;
}

// ---------------------------------------------------------------------------
extern "C" void kernel_launch(void* const* d_in, const int* in_sizes, int n_in,
                              void* d_out, int out_size) {
    const float* in_feat = (const float*)d_in[0];
    const int*   src     = (const int*)d_in[1];
    const int*   dst     = (const int*)d_in[2];
    const float* W       = (const float*)d_in[3];
    const float* b       = (const float*)d_in[4];
    float*       out     = (float*)d_out;

    int n = in_sizes[0] / INF;
    int E = in_sizes[1];

    zero_kernel<<<512, 256>>>();
    degree_kernel<<<2048, 256>>>(src, dst, E);
    scan_local_kernel<<<NBLK, SCAN_B>>>();
    scan_blocks_kernel<<<1, 128>>>();
    scan_add_kernel<<<NBLK, SCAN_B>>>();
    csr_fill_kernel<<<2048, 256>>>(src, dst, E);
    csr_pad_kernel<<<256, 256>>>();
    gemm_mma_kernel<<<(n + 127) / 128, 256>>>(in_feat, W, n);
    aggregate_kernel<<<(n * 32 + 255) / 256, 256>>>(out, b, n);
}

// round 12
// speedup vs baseline: 1.1003x; 1.0503x over previous
#include <cuda_runtime.h>
#include <cuda_fp16.h>

#define NN   100000
#define INF  128
#define OUTF 64
#define NE_MAX 3200000
#define SCAN_B 1024
#define NBLK  ((NN + SCAN_B - 1) / SCAN_B)   // 98
#define WPAD  72

// Scratch (allocation-free rule: __device__ globals)
__device__ __half g_xws_h[(size_t)NN * OUTF]; // fp16 (X@W)*rsqrt(deg_out)
__device__ int    g_deg_out[NN];
__device__ int    g_deg_in[NN];
__device__ int    g_row_off[NN];              // CSR row start (by dst)
__device__ int    g_rank[NE_MAX];             // per-edge rank within dst row
__device__ int    g_csr_src[NE_MAX];
__device__ int    g_blocksum[NBLK];

// ---------------------------------------------------------------------------
__global__ void zero_kernel() {
    int t = blockIdx.x * blockDim.x + threadIdx.x;
    int stride = gridDim.x * blockDim.x;
    for (int j = t; j < NN; j += stride) {
        g_deg_out[j] = 0;
        g_deg_in[j]  = 0;
    }
}

// ---------------------------------------------------------------------------
// Degree histogram + per-edge rank: the deg_in atomic's return value (already
// paid for) becomes the edge's slot within its dst row.
// ---------------------------------------------------------------------------
__global__ void degree_kernel(const int* __restrict__ src,
                              const int* __restrict__ dst, int E) {
    int stride = gridDim.x * blockDim.x;
    for (int e = blockIdx.x * blockDim.x + threadIdx.x; e < E; e += stride) {
        int s = src[e], d = dst[e];
        if ((unsigned)s < NN) atomicAdd(&g_deg_out[s], 1);
        if ((unsigned)d < NN) g_rank[e] = atomicAdd(&g_deg_in[d], 1);
    }
}

// ---------------------------------------------------------------------------
// Exclusive scan of g_deg_in -> g_row_off  (2 passes; block offsets computed
// in-pass by a warp-reduction over the <=98 block sums)
// ---------------------------------------------------------------------------
__global__ __launch_bounds__(SCAN_B) void scan_local_kernel() {
    __shared__ int sm[SCAN_B];
    int tid = threadIdx.x;
    int gid = blockIdx.x * SCAN_B + tid;
    int val = (gid < NN) ? g_deg_in[gid] : 0;
    sm[tid] = val;
    __syncthreads();
    #pragma unroll
    for (int off = 1; off < SCAN_B; off <<= 1) {
        int t = (tid >= off) ? sm[tid - off] : 0;
        __syncthreads();
        sm[tid] += t;
        __syncthreads();
    }
    if (gid < NN) g_row_off[gid] = sm[tid] - val;   // exclusive (local)
    if (tid == SCAN_B - 1) g_blocksum[blockIdx.x] = sm[tid];
}

__global__ __launch_bounds__(SCAN_B) void scan_add_kernel() {
    __shared__ int s_off;
    int tid = threadIdx.x;
    if (tid < 32) {                       // warp 0: prefix of blocksums
        int acc = 0;
        for (int i = tid; i < blockIdx.x; i += 32)
            acc += g_blocksum[i];
        #pragma unroll
        for (int o = 16; o > 0; o >>= 1)
            acc += __shfl_down_sync(0xffffffffu, acc, o);
        if (tid == 0) s_off = acc;
    }
    __syncthreads();
    int gid = blockIdx.x * SCAN_B + tid;
    if (gid < NN)
        g_row_off[gid] += s_off;
}

// ---------------------------------------------------------------------------
// CSR fill, atomic-free: pos = row_off[dst] + rank  (streaming reads only)
// ---------------------------------------------------------------------------
__global__ void csr_fill_kernel(const int* __restrict__ src,
                                const int* __restrict__ dst, int E) {
    int stride = gridDim.x * blockDim.x;
    for (int e = blockIdx.x * blockDim.x + threadIdx.x; e < E; e += stride) {
        int s = src[e], d = dst[e];
        if ((unsigned)s >= NN || (unsigned)d >= NN) continue;
        int pos = __ldg(&g_row_off[d]) + g_rank[e];
        g_csr_src[pos] = s;
    }
}

// ---------------------------------------------------------------------------
// Tensor-core GEMM: xws = fp16( (A @ W) * rsqrt(max(deg_out,1)) )
// mma.sync.m16n8k8 tf32. One warp = 16 rows x 64 cols. (R9 version, trusted.)
// ---------------------------------------------------------------------------
__global__ __launch_bounds__(256) void gemm_mma_kernel(
    const float* __restrict__ A, const float* __restrict__ W, int n) {
    __shared__ unsigned Ws[INF][WPAD];
    int tid = threadIdx.x;
    for (int i = tid; i < INF * OUTF; i += 256) {
        int k = i >> 6, c = i & 63;
        unsigned t;
        asm("cvt.rna.tf32.f32 %0, %1;" : "=r"(t) : "f"(W[i]));
        Ws[k][c] = t;
    }
    __syncthreads();

    int warp = tid >> 5;
    int lane = tid & 31;
    int g  = lane >> 2;
    int tg = lane & 3;
    int row0 = (blockIdx.x * 8 + warp) * 16;

    int r_lo = row0 + g;
    int r_hi = row0 + g + 8;
    int r_lo_c = r_lo < n ? r_lo : n - 1;
    int r_hi_c = r_hi < n ? r_hi : n - 1;
    const float* Alo = A + (size_t)r_lo_c * INF;
    const float* Ahi = A + (size_t)r_hi_c * INF;

    float acc[8][4];
    #pragma unroll
    for (int nt = 0; nt < 8; nt++)
        #pragma unroll
        for (int c = 0; c < 4; c++) acc[nt][c] = 0.f;

    #pragma unroll
    for (int kk = 0; kk < 16; kk++) {
        int k0 = kk * 8;
        float a0f = __ldg(&Alo[k0 + tg]);
        float a1f = __ldg(&Ahi[k0 + tg]);
        float a2f = __ldg(&Alo[k0 + tg + 4]);
        float a3f = __ldg(&Ahi[k0 + tg + 4]);
        unsigned a0, a1, a2, a3;
        asm("cvt.rna.tf32.f32 %0, %1;" : "=r"(a0) : "f"(a0f));
        asm("cvt.rna.tf32.f32 %0, %1;" : "=r"(a1) : "f"(a1f));
        asm("cvt.rna.tf32.f32 %0, %1;" : "=r"(a2) : "f"(a2f));
        asm("cvt.rna.tf32.f32 %0, %1;" : "=r"(a3) : "f"(a3f));
        #pragma unroll
        for (int nt = 0; nt < 8; nt++) {
            unsigned b0 = Ws[k0 + tg][nt * 8 + g];
            unsigned b1 = Ws[k0 + tg + 4][nt * 8 + g];
            asm("mma.sync.aligned.m16n8k8.row.col.f32.tf32.tf32.f32 "
                "{%0,%1,%2,%3}, {%4,%5,%6,%7}, {%8,%9}, {%0,%1,%2,%3};"
                : "+f"(acc[nt][0]), "+f"(acc[nt][1]),
                  "+f"(acc[nt][2]), "+f"(acc[nt][3])
                : "r"(a0), "r"(a1), "r"(a2), "r"(a3), "r"(b0), "r"(b1));
        }
    }

    float s_lo = 1.f, s_hi = 1.f;
    if (r_lo < n) {
        int dg = g_deg_out[r_lo];
        s_lo = rsqrtf((float)(dg > 0 ? dg : 1));
    }
    if (r_hi < n) {
        int dg = g_deg_out[r_hi];
        s_hi = rsqrtf((float)(dg > 0 ? dg : 1));
    }
    #pragma unroll
    for (int nt = 0; nt < 8; nt++) {
        int col = nt * 8 + 2 * tg;
        if (r_lo < n) {
            __half2 h = __floats2half2_rn(acc[nt][0] * s_lo, acc[nt][1] * s_lo);
            *(__half2*)&g_xws_h[(size_t)r_lo * OUTF + col] = h;
        }
        if (r_hi < n) {
            __half2 h = __floats2half2_rn(acc[nt][2] * s_hi, acc[nt][3] * s_hi);
            *(__half2*)&g_xws_h[(size_t)r_hi * OUTF + col] = h;
        }
    }
}

// ---------------------------------------------------------------------------
// Aggregate: one warp per dst node, MLP=8 (R9 scheme, measured best).
// ---------------------------------------------------------------------------
__global__ __launch_bounds__(256) void aggregate_kernel(
    float* __restrict__ out, const float* __restrict__ b, int n) {
    int warp = (blockIdx.x * blockDim.x + threadIdx.x) >> 5;
    if (warp >= n) return;
    int lane = threadIdx.x & 31;

    int start = g_row_off[warp];
    int deg   = g_deg_in[warp];

    float accx = 0.f, accy = 0.f;
    const __half2* base = (const __half2*)g_xws_h;

    for (int e0 = 0; e0 < deg; e0 += 32) {
        int me  = e0 + lane;
        int s   = (me < deg) ? __ldg(&g_csr_src[start + me]) : 0;
        int cnt = deg - e0; if (cnt > 32) cnt = 32;
        int j = 0;
        #pragma unroll 1
        for (; j + 8 <= cnt; j += 8) {
            int si[8];
            #pragma unroll
            for (int q = 0; q < 8; q++)
                si[q] = __shfl_sync(0xffffffffu, s, j + q);
            __half2 v[8];
            #pragma unroll
            for (int q = 0; q < 8; q++)
                v[q] = __ldg(base + (size_t)si[q] * 32 + lane);
            #pragma unroll
            for (int q = 0; q < 8; q++) {
                float2 f = __half22float2(v[q]);
                accx += f.x;
                accy += f.y;
            }
        }
        for (; j < cnt; j++) {
            int sj = __shfl_sync(0xffffffffu, s, j);
            float2 f = __half22float2(__ldg(base + (size_t)sj * 32 + lane));
            accx += f.x;
            accy += f.y;
        }
    }

    float sc = rsqrtf((float)(deg > 0 ? deg : 1));
    float2 bb = __ldg((const float2*)b + lane);
    float2 r;
    r.x = fmaxf(fmaf(accx, sc, bb.x), 0.f);
    r.y = fmaxf(fmaf(accy, sc, bb.y), 0.f);
    ((float2*)out)[(size_t)warp * 32 + lane] = r;
}

// ---------------------------------------------------------------------------
extern "C" void kernel_launch(void* const* d_in, const int* in_sizes, int n_in,
                              void* d_out, int out_size) {
    const float* in_feat = (const float*)d_in[0];
    const int*   src     = (const int*)d_in[1];
    const int*   dst     = (const int*)d_in[2];
    const float* W       = (const float*)d_in[3];
    const float* b       = (const float*)d_in[4];
    float*       out     = (float*)d_out;

    int n = in_sizes[0] / INF;
    int E = in_sizes[1];

    zero_kernel<<<512, 256>>>();
    degree_kernel<<<2048, 256>>>(src, dst, E);
    scan_local_kernel<<<NBLK, SCAN_B>>>();
    scan_add_kernel<<<NBLK, SCAN_B>>>();
    csr_fill_kernel<<<2048, 256>>>(src, dst, E);
    gemm_mma_kernel<<<(n + 127) / 128, 256>>>(in_feat, W, n);
    aggregate_kernel<<<(n * 32 + 255) / 256, 256>>>(out, b, n);
}

// round 13
// speedup vs baseline: 1.1708x; 1.0641x over previous
#include <cuda_runtime.h>
#include <cuda_fp16.h>

#define NN   100000
#define INF  128
#define OUTF 64
#define NE_MAX 3200000
#define SCAN_B 1024
#define NBLK  ((NN + SCAN_B - 1) / SCAN_B)   // 98
#define WPAD  72

// Scratch (allocation-free rule: __device__ globals)
__device__ __half g_xws_h[(size_t)NN * OUTF]; // fp16 (X@W)*rsqrt(deg_out)
__device__ int    g_deg_out[NN];
__device__ int    g_deg_in[NN];
__device__ int    g_row_off[NN];              // CSR row start (by dst)
__device__ int    g_rank[NE_MAX];             // per-edge rank within dst row
__device__ int    g_csr_src[NE_MAX];
__device__ int    g_blocksum[NBLK];

// ---------------------------------------------------------------------------
__global__ void zero_kernel() {
    int t = blockIdx.x * blockDim.x + threadIdx.x;
    int stride = gridDim.x * blockDim.x;
    for (int j = t; j < NN; j += stride) {
        g_deg_out[j] = 0;
        g_deg_in[j]  = 0;
    }
}

// ---------------------------------------------------------------------------
// Degree histogram + per-edge rank (deg_in atomic's return value reused).
// ---------------------------------------------------------------------------
__global__ void degree_kernel(const int* __restrict__ src,
                              const int* __restrict__ dst, int E) {
    int stride = gridDim.x * blockDim.x;
    for (int e = blockIdx.x * blockDim.x + threadIdx.x; e < E; e += stride) {
        int s = src[e], d = dst[e];
        if ((unsigned)s < NN) atomicAdd(&g_deg_out[s], 1);
        if ((unsigned)d < NN) g_rank[e] = atomicAdd(&g_deg_in[d], 1);
    }
}

// ---------------------------------------------------------------------------
// Exclusive scan of g_deg_in -> g_row_off  (2 passes)
// ---------------------------------------------------------------------------
__global__ __launch_bounds__(SCAN_B) void scan_local_kernel() {
    __shared__ int sm[SCAN_B];
    int tid = threadIdx.x;
    int gid = blockIdx.x * SCAN_B + tid;
    int val = (gid < NN) ? g_deg_in[gid] : 0;
    sm[tid] = val;
    __syncthreads();
    #pragma unroll
    for (int off = 1; off < SCAN_B; off <<= 1) {
        int t = (tid >= off) ? sm[tid - off] : 0;
        __syncthreads();
        sm[tid] += t;
        __syncthreads();
    }
    if (gid < NN) g_row_off[gid] = sm[tid] - val;   // exclusive (local)
    if (tid == SCAN_B - 1) g_blocksum[blockIdx.x] = sm[tid];
}

__global__ __launch_bounds__(SCAN_B) void scan_add_kernel() {
    __shared__ int s_off;
    int tid = threadIdx.x;
    if (tid < 32) {                       // warp 0: prefix of blocksums
        int acc = 0;
        for (int i = tid; i < blockIdx.x; i += 32)
            acc += g_blocksum[i];
        #pragma unroll
        for (int o = 16; o > 0; o >>= 1)
            acc += __shfl_down_sync(0xffffffffu, acc, o);
        if (tid == 0) s_off = acc;
    }
    __syncthreads();
    int gid = blockIdx.x * SCAN_B + tid;
    if (gid < NN)
        g_row_off[gid] += s_off;
}

// ---------------------------------------------------------------------------
// CSR fill, atomic-free: pos = row_off[dst] + rank
// ---------------------------------------------------------------------------
__global__ void csr_fill_kernel(const int* __restrict__ src,
                                const int* __restrict__ dst, int E) {
    int stride = gridDim.x * blockDim.x;
    for (int e = blockIdx.x * blockDim.x + threadIdx.x; e < E; e += stride) {
        int s = src[e], d = dst[e];
        if ((unsigned)s >= NN || (unsigned)d >= NN) continue;
        int pos = __ldg(&g_row_off[d]) + g_rank[e];
        g_csr_src[pos] = s;
    }
}

// ---------------------------------------------------------------------------
// Tensor-core GEMM: xws = fp16( (A @ W) * rsqrt(max(deg_out,1)) )
// mma.sync.m16n8k8 tf32. One warp = 16 rows x 64 cols. (trusted R9 version)
// ---------------------------------------------------------------------------
__global__ __launch_bounds__(256) void gemm_mma_kernel(
    const float* __restrict__ A, const float* __restrict__ W, int n) {
    __shared__ unsigned Ws[INF][WPAD];
    int tid = threadIdx.x;
    for (int i = tid; i < INF * OUTF; i += 256) {
        int k = i >> 6, c = i & 63;
        unsigned t;
        asm("cvt.rna.tf32.f32 %0, %1;" : "=r"(t) : "f"(W[i]));
        Ws[k][c] = t;
    }
    __syncthreads();

    int warp = tid >> 5;
    int lane = tid & 31;
    int g  = lane >> 2;
    int tg = lane & 3;
    int row0 = (blockIdx.x * 8 + warp) * 16;

    int r_lo = row0 + g;
    int r_hi = row0 + g + 8;
    int r_lo_c = r_lo < n ? r_lo : n - 1;
    int r_hi_c = r_hi < n ? r_hi : n - 1;
    const float* Alo = A + (size_t)r_lo_c * INF;
    const float* Ahi = A + (size_t)r_hi_c * INF;

    float acc[8][4];
    #pragma unroll
    for (int nt = 0; nt < 8; nt++)
        #pragma unroll
        for (int c = 0; c < 4; c++) acc[nt][c] = 0.f;

    #pragma unroll
    for (int kk = 0; kk < 16; kk++) {
        int k0 = kk * 8;
        float a0f = __ldg(&Alo[k0 + tg]);
        float a1f = __ldg(&Ahi[k0 + tg]);
        float a2f = __ldg(&Alo[k0 + tg + 4]);
        float a3f = __ldg(&Ahi[k0 + tg + 4]);
        unsigned a0, a1, a2, a3;
        asm("cvt.rna.tf32.f32 %0, %1;" : "=r"(a0) : "f"(a0f));
        asm("cvt.rna.tf32.f32 %0, %1;" : "=r"(a1) : "f"(a1f));
        asm("cvt.rna.tf32.f32 %0, %1;" : "=r"(a2) : "f"(a2f));
        asm("cvt.rna.tf32.f32 %0, %1;" : "=r"(a3) : "f"(a3f));
        #pragma unroll
        for (int nt = 0; nt < 8; nt++) {
            unsigned b0 = Ws[k0 + tg][nt * 8 + g];
            unsigned b1 = Ws[k0 + tg + 4][nt * 8 + g];
            asm("mma.sync.aligned.m16n8k8.row.col.f32.tf32.tf32.f32 "
                "{%0,%1,%2,%3}, {%4,%5,%6,%7}, {%8,%9}, {%0,%1,%2,%3};"
                : "+f"(acc[nt][0]), "+f"(acc[nt][1]),
                  "+f"(acc[nt][2]), "+f"(acc[nt][3])
                : "r"(a0), "r"(a1), "r"(a2), "r"(a3), "r"(b0), "r"(b1));
        }
    }

    float s_lo = 1.f, s_hi = 1.f;
    if (r_lo < n) {
        int dg = g_deg_out[r_lo];
        s_lo = rsqrtf((float)(dg > 0 ? dg : 1));
    }
    if (r_hi < n) {
        int dg = g_deg_out[r_hi];
        s_hi = rsqrtf((float)(dg > 0 ? dg : 1));
    }
    #pragma unroll
    for (int nt = 0; nt < 8; nt++) {
        int col = nt * 8 + 2 * tg;
        if (r_lo < n) {
            __half2 h = __floats2half2_rn(acc[nt][0] * s_lo, acc[nt][1] * s_lo);
            *(__half2*)&g_xws_h[(size_t)r_lo * OUTF + col] = h;
        }
        if (r_hi < n) {
            __half2 h = __floats2half2_rn(acc[nt][2] * s_hi, acc[nt][3] * s_hi);
            *(__half2*)&g_xws_h[(size_t)r_hi * OUTF + col] = h;
        }
    }
}

// ---------------------------------------------------------------------------
// Aggregate: one warp per dst node, MLP=8 (measured best).
// ---------------------------------------------------------------------------
__global__ __launch_bounds__(256) void aggregate_kernel(
    float* __restrict__ out, const float* __restrict__ b, int n) {
    int warp = (blockIdx.x * blockDim.x + threadIdx.x) >> 5;
    if (warp >= n) return;
    int lane = threadIdx.x & 31;

    int start = g_row_off[warp];
    int deg   = g_deg_in[warp];

    float accx = 0.f, accy = 0.f;
    const __half2* base = (const __half2*)g_xws_h;

    for (int e0 = 0; e0 < deg; e0 += 32) {
        int me  = e0 + lane;
        int s   = (me < deg) ? __ldg(&g_csr_src[start + me]) : 0;
        int cnt = deg - e0; if (cnt > 32) cnt = 32;
        int j = 0;
        #pragma unroll 1
        for (; j + 8 <= cnt; j += 8) {
            int si[8];
            #pragma unroll
            for (int q = 0; q < 8; q++)
                si[q] = __shfl_sync(0xffffffffu, s, j + q);
            __half2 v[8];
            #pragma unroll
            for (int q = 0; q < 8; q++)
                v[q] = __ldg(base + (size_t)si[q] * 32 + lane);
            #pragma unroll
            for (int q = 0; q < 8; q++) {
                float2 f = __half22float2(v[q]);
                accx += f.x;
                accy += f.y;
            }
        }
        for (; j < cnt; j++) {
            int sj = __shfl_sync(0xffffffffu, s, j);
            float2 f = __half22float2(__ldg(base + (size_t)sj * 32 + lane));
            accx += f.x;
            accy += f.y;
        }
    }

    float sc = rsqrtf((float)(deg > 0 ? deg : 1));
    float2 bb = __ldg((const float2*)b + lane);
    float2 r;
    r.x = fmaxf(fmaf(accx, sc, bb.x), 0.f);
    r.y = fmaxf(fmaf(accy, sc, bb.y), 0.f);
    ((float2*)out)[(size_t)warp * 32 + lane] = r;
}

// ---------------------------------------------------------------------------
// Fork/join: GEMM (needs only deg_out) overlaps the scan+fill chain
// (needs only deg_in/rank). Kernels identical to R12; only topology changed.
// ---------------------------------------------------------------------------
extern "C" void kernel_launch(void* const* d_in, const int* in_sizes, int n_in,
                              void* d_out, int out_size) {
    const float* in_feat = (const float*)d_in[0];
    const int*   src     = (const int*)d_in[1];
    const int*   dst     = (const int*)d_in[2];
    const float* W       = (const float*)d_in[3];
    const float* b       = (const float*)d_in[4];
    float*       out     = (float*)d_out;

    int n = in_sizes[0] / INF;
    int E = in_sizes[1];

    static cudaStream_t sA = nullptr;
    static cudaEvent_t  evD = nullptr, evF = nullptr;
    if (!sA) {   // one-time infra setup (first call is outside graph capture)
        cudaStreamCreateWithFlags(&sA, cudaStreamNonBlocking);
        cudaEventCreateWithFlags(&evD, cudaEventDisableTiming);
        cudaEventCreateWithFlags(&evF, cudaEventDisableTiming);
    }

    zero_kernel<<<512, 256>>>();
    degree_kernel<<<2048, 256>>>(src, dst, E);
    cudaEventRecord(evD, 0);

    // side stream: CSR build chain (scan -> fill)
    cudaStreamWaitEvent(sA, evD, 0);
    scan_local_kernel<<<NBLK, SCAN_B, 0, sA>>>();
    scan_add_kernel<<<NBLK, SCAN_B, 0, sA>>>();
    csr_fill_kernel<<<2048, 256, 0, sA>>>(src, dst, E);
    cudaEventRecord(evF, sA);

    // main stream: GEMM overlaps the CSR build
    gemm_mma_kernel<<<(n + 127) / 128, 256>>>(in_feat, W, n);

    cudaStreamWaitEvent(0, evF, 0);
    aggregate_kernel<<<(n * 32 + 255) / 256, 256>>>(out, b, n);
}